// round 1
// baseline (speedup 1.0000x reference)
#include <cuda_runtime.h>
#include <math.h>

#define Hn   1024
#define En   1024
#define Tn   4096
#define Vn   50257
#define INPn 2049

// ---- scratch (no allocations allowed) ----
__device__ float g_att[En];        // column sums of hiddens
__device__ float g_preact[4*Hn];   // gate pre-activations: [i, f, g, o]
__device__ float g_h[Hn];          // LSTM output h
__device__ float g_logits[Vn];     // h @ dim_out
__device__ float g_stats[2];       // {max, 1/sum}

struct GateParams {
    const float* Wi[4];
    const float* Wh[4];
    const float* bi[4];
    const float* bh[4];
};

// Zero the accumulators used with atomicAdd.
__global__ void k_init() {
    int i = blockIdx.x * blockDim.x + threadIdx.x;
    int stride = gridDim.x * blockDim.x;
    if (i < En) g_att[i] = 0.f;
    for (int v = i; v < Vn; v += stride) g_logits[v] = 0.f;
}

// att_result = column sum of hiddens [T, E] (softmax over size-1 axis == all ones)
__global__ void k_colsum(const float* __restrict__ hid) {
    int e  = blockIdx.x * 128 + threadIdx.x;   // column
    int t0 = blockIdx.y * 128;                 // row chunk
    float s = 0.f;
    #pragma unroll 8
    for (int t = 0; t < 128; t++)
        s += hid[(size_t)(t0 + t) * En + e];
    atomicAdd(&g_att[e], s);
}

// 8 matvecs: one warp per (gate, row). y = Wi@x + bi + Wh@cur_h + bh
__global__ void k_gates(GateParams gp,
                        const float* __restrict__ sen,
                        const float* __restrict__ curh,
                        const int*   __restrict__ pos) {
    int w    = (blockIdx.x * blockDim.x + threadIdx.x) >> 5;
    int lane = threadIdx.x & 31;
    if (w >= 4 * Hn) return;
    int g = w >> 10;
    int r = w & (Hn - 1);

    // pos_index dtype-defensive read: small bit pattern -> int, else float bits
    int ib = __ldg(pos);
    float posv = ((unsigned)ib < (1u << 20)) ? (float)ib : __int_as_float(ib);

    const float* Wi = gp.Wi[g] + (size_t)r * INPn;
    const float* Wh = gp.Wh[g] + (size_t)r * Hn;

    float acc = 0.f;
    #pragma unroll 4
    for (int c = lane; c < INPn; c += 32) {
        float xv = (c < En) ? __ldg(&sen[c])
                 : (c < En + Hn) ? g_att[c - En]
                 : posv;
        acc += Wi[c] * xv;
    }
    #pragma unroll 4
    for (int c = lane; c < Hn; c += 32)
        acc += Wh[c] * __ldg(&curh[c]);

    #pragma unroll
    for (int o = 16; o; o >>= 1)
        acc += __shfl_down_sync(0xffffffffu, acc, o);

    if (lane == 0)
        g_preact[g * Hn + r] = acc + __ldg(&gp.bi[g][r]) + __ldg(&gp.bh[g][r]);
}

// LSTM cell activations -> h
__global__ void k_act(const float* __restrict__ cell) {
    int r = blockIdx.x * blockDim.x + threadIdx.x;
    if (r >= Hn) return;
    float yi = g_preact[r];
    float yf = g_preact[Hn + r];
    float yg = g_preact[2 * Hn + r];
    float yo = g_preact[3 * Hn + r];
    float i = 1.f / (1.f + expf(-yi));
    float f = 1.f / (1.f + expf(-yf));
    float g = tanhf(yg);
    float o = 1.f / (1.f + expf(-yo));
    float c = f * cell[r] + i * g;
    g_h[r] = o * tanhf(c);
}

// logits[v] = sum_h h[h] * dim_out[h*V + v]; split h into gridDim.y chunks of 256
__global__ void k_logits(const float* __restrict__ dout) {
    __shared__ float sh[256];
    int h0 = blockIdx.y * 256;
    sh[threadIdx.x] = g_h[h0 + threadIdx.x];
    __syncthreads();
    int v = blockIdx.x * 256 + threadIdx.x;
    if (v >= Vn) return;
    const float* p = dout + (size_t)h0 * Vn + v;
    float acc = 0.f;
    #pragma unroll 8
    for (int h = 0; h < 256; h++)
        acc += sh[h] * p[(size_t)h * Vn];
    atomicAdd(&g_logits[v], acc);
}

// single-block softmax stats: max + sum of exp
__global__ void k_stats() {
    __shared__ float red[1024];
    int t = threadIdx.x;
    float m = -INFINITY;
    for (int v = t; v < Vn; v += 1024) m = fmaxf(m, g_logits[v]);
    red[t] = m; __syncthreads();
    for (int s = 512; s; s >>= 1) {
        if (t < s) red[t] = fmaxf(red[t], red[t + s]);
        __syncthreads();
    }
    float mx = red[0];
    __syncthreads();
    float sum = 0.f;
    for (int v = t; v < Vn; v += 1024) sum += expf(g_logits[v] - mx);
    red[t] = sum; __syncthreads();
    for (int s = 512; s; s >>= 1) {
        if (t < s) red[t] += red[t + s];
        __syncthreads();
    }
    if (t == 0) { g_stats[0] = mx; g_stats[1] = 1.f / red[0]; }
}

__global__ void k_norm(float* __restrict__ out) {
    int v = blockIdx.x * blockDim.x + threadIdx.x;
    if (v < Vn)
        out[v] = expf(g_logits[v] - g_stats[0]) * g_stats[1];
}

extern "C" void kernel_launch(void* const* d_in, const int* in_sizes, int n_in,
                              void* d_out, int out_size) {
    const float* sen  = (const float*)d_in[0];
    const float* hid  = (const float*)d_in[1];
    const float* dout = (const float*)d_in[2];
    GateParams gp;
    for (int g = 0; g < 4; g++) {
        gp.Wi[g] = (const float*)d_in[3 + 4 * g];
        gp.Wh[g] = (const float*)d_in[4 + 4 * g];
        gp.bi[g] = (const float*)d_in[5 + 4 * g];
        gp.bh[g] = (const float*)d_in[6 + 4 * g];
    }
    const float* curh = (const float*)d_in[19];
    const float* curc = (const float*)d_in[20];
    const int*   pos  = (const int*)d_in[21];
    float* out = (float*)d_out;

    k_init<<<64, 256>>>();
    k_colsum<<<dim3(En / 128, Tn / 128), 128>>>(hid);
    k_gates<<<(4 * Hn * 32 + 255) / 256, 256>>>(gp, sen, curh, pos);
    k_act<<<(Hn + 255) / 256, 256>>>(curc);
    k_logits<<<dim3((Vn + 255) / 256, 4), 256>>>(dout);
    k_stats<<<1, 1024>>>();
    k_norm<<<(Vn + 255) / 256, 256>>>(out);
}